// round 10
// baseline (speedup 1.0000x reference)
#include <cuda_runtime.h>
#include <cuda_bf16.h>
#include <cstdint>

// Problem constants
#define N_TOK   16384          // B*S = 4*4096
#define D_DIM   2048
#define E_EXP   64
#define CAP     256            // N * 1.0 / E

// GEMM tiling (mma.sync m16n8k8 tf32)
#define BMt     128            // tokens per CTA
#define BNt     64             // experts per CTA (all)
#define BKt     32             // fp32 K per chunk
#define NCHUNK  (D_DIM / BKt)  // 64
#define ASTR    36             // smem row stride (floats): conflict-free frag access

// Scratch (no allocations allowed)
__device__ float    g_aff[E_EXP * N_TOK];            // affinity [E][N]
__device__ int      g_counts[N_TOK];
__device__ unsigned g_sel_idx[E_EXP * CAP];
__device__ float    g_sel_prob[E_EXP * CAP];
__device__ float    g_dummy[N_TOK * E_EXP];

// ---------------------------------------------------------------------------
// helpers
// ---------------------------------------------------------------------------
// cvt.rna.tf32.f32 requires a .b32 destination (fp32 bit pattern, low 13
// mantissa bits cleared).
__device__ __forceinline__ uint32_t tf32_bits(float x) {
    uint32_t r;
    asm("cvt.rna.tf32.f32 %0, %1;" : "=r"(r) : "f"(x));
    return r;
}
__device__ __forceinline__ void split(float x, uint32_t& hi, uint32_t& lo) {
    hi = tf32_bits(x);
    lo = tf32_bits(x - __uint_as_float(hi));
}
__device__ __forceinline__ void mma_tf32(float* c, const uint32_t* a, const uint32_t* b) {
    asm volatile(
        "mma.sync.aligned.m16n8k8.row.col.f32.tf32.tf32.f32 "
        "{%0,%1,%2,%3}, {%4,%5,%6,%7}, {%8,%9}, {%0,%1,%2,%3};"
        : "+f"(c[0]), "+f"(c[1]), "+f"(c[2]), "+f"(c[3])
        : "r"(a[0]), "r"(a[1]), "r"(a[2]), "r"(a[3]), "r"(b[0]), "r"(b[1]));
}

// Sortable key transforms (monotone float <-> uint32)
__device__ __forceinline__ unsigned f2k(float f) {
    unsigned u = __float_as_uint(f);
    return (u >> 31) ? ~u : (u | 0x80000000u);
}
__device__ __forceinline__ float k2f(unsigned k) {
    unsigned u = (k & 0x80000000u) ? (k ^ 0x80000000u) : ~k;
    return __uint_as_float(u);
}

// ---------------------------------------------------------------------------
// Kernel 0: init outputs + counts (out poisoned to 0xAA by harness)
// ---------------------------------------------------------------------------
__global__ void init_kernel(float* __restrict__ out, int out_size, int total_main) {
    int base = (blockIdx.x * blockDim.x + threadIdx.x) * 4;
    #pragma unroll
    for (int j = 0; j < 4; j++) {
        int i = base + j;
        if (i < out_size) out[i] = (i < total_main) ? 0.0f : 256.0f;
    }
    int n = blockIdx.x * blockDim.x + threadIdx.x;
    if (n < N_TOK) g_counts[n] = 0;
}

// ---------------------------------------------------------------------------
// Kernel 1: TF32x3 mma.sync GEMM.  g_aff[e][n] = sum_d tok[n][d]*w[e][d]
// 128 CTAs x 512 threads (16 warps, 4x4 grid, 32x16 warp tiles -> 4
// warps/SMSP for latency hiding). Same 128x64 CTA tile and smem layout as
// the proven R8 config; hi/lo tf32 split consumer-side in registers.
// ---------------------------------------------------------------------------
#define GEMM_SMEM ((2 * BMt * ASTR + 2 * BNt * ASTR) * 4)   // 55296 B

__global__ void __launch_bounds__(512)
gemm_mma(const float* __restrict__ tokens, const float* __restrict__ wsel) {
    extern __shared__ float sm[];
    float* As = sm;                       // [2][BMt*ASTR]
    float* Bs = sm + 2 * BMt * ASTR;      // [2][BNt*ASTR]

    const int t    = threadIdx.x;
    const int lane = t & 31;
    const int wid  = t >> 5;              // 0..15
    const int warp_m = wid & 3;           // 0..3 -> token offset *32
    const int warp_n = wid >> 2;          // 0..3 -> expert offset *16
    const int g  = lane >> 2;             // 0..7
    const int tg = lane & 3;              // 0..3
    const int n0 = blockIdx.x * BMt;

    // gmem load coords: A 2 float4/thread (128x8 f4), B 1 float4/thread (64x8 f4)
    int arow[2], akq[2];
    #pragma unroll
    for (int r = 0; r < 2; r++) { int i = t + r * 512; arow[r] = i >> 3; akq[r] = i & 7; }
    const int browB = t >> 3;             // 0..63
    const int bkqB  = t & 7;

    float4 pa[2], pb;

    float c[2][2][4];                     // [mi][ni][quad]
    #pragma unroll
    for (int mi = 0; mi < 2; mi++)
        #pragma unroll
        for (int ni = 0; ni < 2; ni++)
            #pragma unroll
            for (int q = 0; q < 4; q++) c[mi][ni][q] = 0.0f;

    // ---- prefetch chunk 0 + store to buf 0 ----
    #pragma unroll
    for (int r = 0; r < 2; r++)
        pa[r] = *(const float4*)(tokens + (size_t)(n0 + arow[r]) * D_DIM + akq[r] * 4);
    pb = *(const float4*)(wsel + (size_t)browB * D_DIM + bkqB * 4);
    #pragma unroll
    for (int r = 0; r < 2; r++)
        *(float4*)(As + arow[r] * ASTR + akq[r] * 4) = pa[r];
    *(float4*)(Bs + browB * ASTR + bkqB * 4) = pb;
    __syncthreads();

    for (int ch = 0; ch < NCHUNK; ch++) {
        const int b = ch & 1;
        // prefetch next chunk (overlaps with compute below)
        if (ch < NCHUNK - 1) {
            const int c0 = (ch + 1) * BKt;
            #pragma unroll
            for (int r = 0; r < 2; r++)
                pa[r] = *(const float4*)(tokens + (size_t)(n0 + arow[r]) * D_DIM + c0 + akq[r] * 4);
            pb = *(const float4*)(wsel + (size_t)browB * D_DIM + c0 + bkqB * 4);
        }

        const float* Ab = As + b * (BMt * ASTR);
        const float* Bb = Bs + b * (BNt * ASTR);
        #pragma unroll
        for (int ks = 0; ks < 4; ks++) {
            const int kc = ks * 8;
            uint32_t ahi[2][4], alo[2][4], bhi[2][2], blo[2][2];
            #pragma unroll
            for (int mi = 0; mi < 2; mi++) {
                int r0 = warp_m * 32 + mi * 16 + g;
                split(Ab[r0 * ASTR + kc + tg],           ahi[mi][0], alo[mi][0]);
                split(Ab[(r0 + 8) * ASTR + kc + tg],     ahi[mi][1], alo[mi][1]);
                split(Ab[r0 * ASTR + kc + tg + 4],       ahi[mi][2], alo[mi][2]);
                split(Ab[(r0 + 8) * ASTR + kc + tg + 4], ahi[mi][3], alo[mi][3]);
            }
            #pragma unroll
            for (int ni = 0; ni < 2; ni++) {
                int cb = warp_n * 16 + ni * 8 + g;
                split(Bb[cb * ASTR + kc + tg],     bhi[ni][0], blo[ni][0]);
                split(Bb[cb * ASTR + kc + tg + 4], bhi[ni][1], blo[ni][1]);
            }
            #pragma unroll
            for (int mi = 0; mi < 2; mi++)
                #pragma unroll
                for (int ni = 0; ni < 2; ni++) {
                    mma_tf32(c[mi][ni], ahi[mi], bhi[ni]);
                    mma_tf32(c[mi][ni], ahi[mi], blo[ni]);
                    mma_tf32(c[mi][ni], alo[mi], bhi[ni]);
                }
        }
        __syncthreads();
        if (ch < NCHUNK - 1) {
            float* Aw = As + (b ^ 1) * (BMt * ASTR);
            float* Bw = Bs + (b ^ 1) * (BNt * ASTR);
            #pragma unroll
            for (int r = 0; r < 2; r++)
                *(float4*)(Aw + arow[r] * ASTR + akq[r] * 4) = pa[r];
            *(float4*)(Bw + browB * ASTR + bkqB * 4) = pb;
            __syncthreads();
        }
    }

    // ---- epilogue: c[mi][ni] -> g_aff[e][token] ----
    #pragma unroll
    for (int mi = 0; mi < 2; mi++) {
        int tm = n0 + warp_m * 32 + mi * 16;
        #pragma unroll
        for (int ni = 0; ni < 2; ni++) {
            int en = warp_n * 16 + ni * 8 + 2 * tg;
            g_aff[(size_t)en       * N_TOK + tm + g    ] = c[mi][ni][0];
            g_aff[(size_t)(en + 1) * N_TOK + tm + g    ] = c[mi][ni][1];
            g_aff[(size_t)en       * N_TOK + tm + g + 8] = c[mi][ni][2];
            g_aff[(size_t)(en + 1) * N_TOK + tm + g + 8] = c[mi][ni][3];
        }
    }
}

// ---------------------------------------------------------------------------
// Kernel 2: per-expert exact top-256 + softmax -> compact lists + counts.
// One CTA (1024 threads) per expert; smem score cache.
// ---------------------------------------------------------------------------
__global__ void __launch_bounds__(1024)
topk_kernel() {
    extern __shared__ float scores[];          // N_TOK floats = 64 KB

    __shared__ unsigned hist[2048];
    __shared__ unsigned gsum[64];
    __shared__ unsigned wred[32];
    __shared__ float    fwred[32];
    __shared__ unsigned eqidx[256];
    __shared__ unsigned s_neq, s_na;
    __shared__ unsigned s_b1, s_ab1, s_b2, s_ab2, s_T, s_needeq, s_maxkey;
    __shared__ float    s_m, s_scoreT, s_inv;

    const int e = blockIdx.x;
    const int t = threadIdx.x;
    const float* row = g_aff + (size_t)e * N_TOK;

    // ---- pass 1: load + histogram (top 11 bits) + row max ----
    for (int i = t; i < 2048; i += 1024) hist[i] = 0;
    if (t == 0) { s_neq = 0; s_na = 0; }
    __syncthreads();

    unsigned kmax = 0;
    for (int i = t; i < N_TOK; i += 1024) {
        float s = row[i];
        scores[i] = s;
        unsigned k = f2k(s);
        kmax = max(kmax, k);
        unsigned bin = k >> 21;
        unsigned mask = __match_any_sync(0xFFFFFFFFu, bin);
        int leader = __ffs(mask) - 1;
        if ((t & 31) == leader) atomicAdd(&hist[bin], (unsigned)__popc(mask));
    }
    #pragma unroll
    for (int o = 16; o; o >>= 1) kmax = max(kmax, __shfl_xor_sync(0xFFFFFFFFu, kmax, o));
    if ((t & 31) == 0) wred[t >> 5] = kmax;
    __syncthreads();
    if (t < 32) {
        unsigned v = wred[t];
        #pragma unroll
        for (int o = 16; o; o >>= 1) v = max(v, __shfl_xor_sync(0xFFFFFFFFu, v, o));
        if (t == 0) s_maxkey = v;
    }
    if (t < 64) { unsigned s = 0; for (int j = 0; j < 32; j++) s += hist[t * 32 + j]; gsum[t] = s; }
    __syncthreads();
    if (t == 0) {
        unsigned need = CAP, cum = 0; int g = 63;
        for (; g > 0; g--) { if (cum + gsum[g] >= need) break; cum += gsum[g]; }
        int b = g * 32 + 31;
        for (; b > g * 32; b--) { if (cum + hist[b] >= need) break; cum += hist[b]; }
        s_b1 = (unsigned)b; s_ab1 = cum;
    }
    __syncthreads();
    const unsigned b1 = s_b1, ab1 = s_ab1;

    // ---- pass 2: next 11 bits within bin b1 ----
    __syncthreads();
    for (int i = t; i < 2048; i += 1024) hist[i] = 0;
    __syncthreads();
    for (int i = t; i < N_TOK; i += 1024) {
        unsigned k = f2k(scores[i]);
        if ((k >> 21) == b1) atomicAdd(&hist[(k >> 10) & 0x7FFu], 1u);
    }
    __syncthreads();
    if (t < 64) { unsigned s = 0; for (int j = 0; j < 32; j++) s += hist[t * 32 + j]; gsum[t] = s; }
    __syncthreads();
    if (t == 0) {
        unsigned need = CAP - ab1, cum = 0; int g = 63;
        for (; g > 0; g--) { if (cum + gsum[g] >= need) break; cum += gsum[g]; }
        int b = g * 32 + 31;
        for (; b > g * 32; b--) { if (cum + hist[b] >= need) break; cum += hist[b]; }
        s_b2 = (unsigned)b; s_ab2 = ab1 + cum;
    }
    __syncthreads();
    const unsigned b2 = s_b2, ab2 = s_ab2;
    const unsigned pref = (b1 << 11) | b2;

    // ---- pass 3: low 10 bits ----
    __syncthreads();
    if (t < 1024) hist[t] = 0;
    __syncthreads();
    for (int i = t; i < N_TOK; i += 1024) {
        unsigned k = f2k(scores[i]);
        if ((k >> 10) == pref) atomicAdd(&hist[k & 0x3FFu], 1u);
    }
    __syncthreads();
    if (t < 32) { unsigned s = 0; for (int j = 0; j < 32; j++) s += hist[t * 32 + j]; gsum[t] = s; }
    __syncthreads();
    if (t == 0) {
        unsigned need = CAP - ab2, cum = 0; int g = 31;
        for (; g > 0; g--) { if (cum + gsum[g] >= need) break; cum += gsum[g]; }
        int b = g * 32 + 31;
        for (; b > g * 32; b--) { if (cum + hist[b] >= need) break; cum += hist[b]; }
        unsigned T = (pref << 10) | (unsigned)b;
        s_T = T;
        s_needeq = CAP - (ab2 + cum);
    }
    __syncthreads();
    const unsigned T = s_T;
    const unsigned need_eq = s_needeq;

    // ---- collect indices with key == T ----
    for (int i = t; i < N_TOK; i += 1024) {
        if (f2k(scores[i]) == T) {
            unsigned p = atomicAdd(&s_neq, 1u);
            if (p < 256) eqidx[p] = (unsigned)i;
        }
    }
    __syncthreads();
    if (t == 0) {
        unsigned ne = min(s_neq, 256u);
        for (unsigned s = 0; s < need_eq && s < ne; s++) {  // smallest indices first
            unsigned mi = s;
            for (unsigned j = s + 1; j < ne; j++)
                if (eqidx[j] < eqidx[mi]) mi = j;
            unsigned tmp = eqidx[s]; eqidx[s] = eqidx[mi]; eqidx[mi] = tmp;
        }
        s_m = k2f(s_maxkey);
        s_scoreT = k2f(T);
    }
    __syncthreads();
    const float m = s_m;

    // ---- softmax denominator over selected set ----
    float part = 0.0f;
    for (int i = t; i < N_TOK; i += 1024) {
        if (f2k(scores[i]) > T) part += expf(scores[i] - m);
    }
    #pragma unroll
    for (int o = 16; o; o >>= 1) part += __shfl_xor_sync(0xFFFFFFFFu, part, o);
    if ((t & 31) == 0) fwred[t >> 5] = part;
    __syncthreads();
    if (t < 32) {
        float v = fwred[t];
        #pragma unroll
        for (int o = 16; o; o >>= 1) v += __shfl_xor_sync(0xFFFFFFFFu, v, o);
        if (t == 0) s_inv = 1.0f / (v + (float)need_eq * expf(s_scoreT - m));
    }
    __syncthreads();
    const float inv = s_inv;

    // ---- compact output ----
    unsigned* sel_i = g_sel_idx  + (size_t)e * CAP;
    float*    sel_p = g_sel_prob + (size_t)e * CAP;
    for (int i = t; i < N_TOK; i += 1024) {
        if (f2k(scores[i]) > T) {
            unsigned pos = atomicAdd(&s_na, 1u);
            sel_i[pos] = (unsigned)i;
            sel_p[pos] = expf(scores[i] - m) * inv;
            atomicAdd(&g_counts[i], 1);
        }
    }
    __syncthreads();
    unsigned ne = min(s_neq, 256u);
    if (t < (int)need_eq && t < (int)ne) {
        unsigned i = eqidx[t];
        unsigned pos = (CAP - need_eq) + t;
        sel_i[pos] = i;
        sel_p[pos] = expf(s_scoreT - m) * inv;
        atomicAdd(&g_counts[i], 1);
    }
}

// ---------------------------------------------------------------------------
// Kernel 3: emit — scatter compact lists into [N,E] outputs with count divide
// ---------------------------------------------------------------------------
__global__ void emit_kernel(float* __restrict__ out_w, float* __restrict__ out_a) {
    int idx = blockIdx.x * blockDim.x + threadIdx.x;
    if (idx >= E_EXP * CAP) return;
    int e = idx >> 8;                                  // CAP == 256
    unsigned i = g_sel_idx[idx];
    float p = g_sel_prob[idx];
    int c = g_counts[i];
    out_w[(size_t)i * E_EXP + e] = p / (float)c;
    out_a[(size_t)i * E_EXP + e] = 1.0f;
}

// ---------------------------------------------------------------------------
// launch
// ---------------------------------------------------------------------------
extern "C" void kernel_launch(void* const* d_in, const int* in_sizes, int n_in,
                              void* d_out, int out_size) {
    const float* tokens = (const float*)d_in[0];   // [4,4096,2048] fp32
    const float* wsel   = (const float*)d_in[1];   // [64,2048] fp32
    float* out = (float*)d_out;

    const int total_main = 2 * N_TOK * E_EXP;

    float* out_w;
    float* out_a;
    float* dummy_ptr = nullptr;
    cudaGetSymbolAddress((void**)&dummy_ptr, g_dummy);
    if (out_size >= total_main) {
        out_w = out;
        out_a = out + (size_t)N_TOK * E_EXP;
    } else if (out_size >= N_TOK * E_EXP) {
        out_w = out;
        out_a = dummy_ptr;
    } else {
        out_w = dummy_ptr;
        out_a = dummy_ptr;
    }

    cudaFuncSetAttribute(gemm_mma, cudaFuncAttributeMaxDynamicSharedMemorySize, GEMM_SMEM);
    cudaFuncSetAttribute(topk_kernel, cudaFuncAttributeMaxDynamicSharedMemorySize,
                         N_TOK * sizeof(float));

    // 0) init outputs + counts
    {
        int quads = (out_size + 3) / 4;
        int blocks = (quads + 255) / 256;
        init_kernel<<<blocks, 256>>>(out, out_size, total_main);
    }
    // 1) TF32x3 mma.sync GEMM -> g_aff
    gemm_mma<<<N_TOK / BMt, 512, GEMM_SMEM>>>(tokens, wsel);
    // 2) per-expert top-256 + softmax -> compact lists + counts
    topk_kernel<<<E_EXP, 1024, N_TOK * sizeof(float)>>>();
    // 3) emit outputs
    emit_kernel<<<(E_EXP * CAP + 127) / 128, 128>>>(out_w, out_a);
}

// round 14
// speedup vs baseline: 1.1413x; 1.1413x over previous
#include <cuda_runtime.h>
#include <cuda_bf16.h>
#include <cstdint>

// Problem constants
#define N_TOK   16384          // B*S = 4*4096
#define D_DIM   2048
#define E_EXP   64
#define CAP     256            // N * 1.0 / E

// GEMM tiling (mma.sync m16n8k8 tf32) — R8 structure + cp.async pipeline
#define BMt     128            // tokens per CTA
#define BNt     64             // experts per CTA (all)
#define BKt     32             // fp32 K per chunk
#define NCHUNK  (D_DIM / BKt)  // 64
#define ASTR    36             // smem row stride (floats): conflict-free frags
#define STAGES  4
#define A_FLOATS (BMt * ASTR)                 // 4608
#define B_FLOATS (BNt * ASTR)                 // 2304
#define STG_FLOATS (A_FLOATS + B_FLOATS)      // 6912
#define GEMM_SMEM (STAGES * STG_FLOATS * 4)   // 110592 B

// topk candidate list
#define CANDMAX 8192

// Scratch (no allocations allowed)
__device__ float    g_aff[E_EXP * N_TOK];            // affinity [E][N]
__device__ int      g_counts[N_TOK];
__device__ unsigned g_sel_idx[E_EXP * CAP];
__device__ float    g_sel_prob[E_EXP * CAP];
__device__ float    g_dummy[N_TOK * E_EXP];

// ---------------------------------------------------------------------------
// helpers
// ---------------------------------------------------------------------------
__device__ __forceinline__ uint32_t tf32_bits(float x) {
    uint32_t r;
    asm("cvt.rna.tf32.f32 %0, %1;" : "=r"(r) : "f"(x));
    return r;
}
__device__ __forceinline__ void split(float x, uint32_t& hi, uint32_t& lo) {
    hi = tf32_bits(x);
    lo = tf32_bits(x - __uint_as_float(hi));
}
__device__ __forceinline__ void mma_tf32(float* c, const uint32_t* a, const uint32_t* b) {
    asm volatile(
        "mma.sync.aligned.m16n8k8.row.col.f32.tf32.tf32.f32 "
        "{%0,%1,%2,%3}, {%4,%5,%6,%7}, {%8,%9}, {%0,%1,%2,%3};"
        : "+f"(c[0]), "+f"(c[1]), "+f"(c[2]), "+f"(c[3])
        : "r"(a[0]), "r"(a[1]), "r"(a[2]), "r"(a[3]), "r"(b[0]), "r"(b[1]));
}
__device__ __forceinline__ uint32_t smem_u32(const void* p) {
    return (uint32_t)__cvta_generic_to_shared(p);
}
#define CP_ASYNC16(dst_u32, src) \
    asm volatile("cp.async.cg.shared.global [%0], [%1], 16;" :: "r"(dst_u32), "l"(src) : "memory")
#define CP_COMMIT()  asm volatile("cp.async.commit_group;" ::: "memory")
#define CP_WAIT(n)   asm volatile("cp.async.wait_group %0;" :: "n"(n) : "memory")

// Sortable key transforms (monotone float <-> uint32)
__device__ __forceinline__ unsigned f2k(float f) {
    unsigned u = __float_as_uint(f);
    return (u >> 31) ? ~u : (u | 0x80000000u);
}
__device__ __forceinline__ float k2f(unsigned k) {
    unsigned u = (k & 0x80000000u) ? (k ^ 0x80000000u) : ~k;
    return __uint_as_float(u);
}

// ---------------------------------------------------------------------------
// Kernel 0: init outputs + counts (out poisoned to 0xAA by harness)
// ---------------------------------------------------------------------------
__global__ void init_kernel(float* __restrict__ out, int out_size, int total_main) {
    int base = (blockIdx.x * blockDim.x + threadIdx.x) * 4;
    #pragma unroll
    for (int j = 0; j < 4; j++) {
        int i = base + j;
        if (i < out_size) out[i] = (i < total_main) ? 0.0f : 256.0f;
    }
    int n = blockIdx.x * blockDim.x + threadIdx.x;
    if (n < N_TOK) g_counts[n] = 0;
}

// ---------------------------------------------------------------------------
// Kernel 1: TF32x3 mma.sync GEMM with 4-stage cp.async pipeline.
// 128 CTAs x 256 threads (8 warps, 4x2 grid, 32x32 warp tiles) — the proven
// R8 compute structure; only the loader changed (register prefetch ->
// cp.async multi-stage).
// ---------------------------------------------------------------------------
__global__ void __launch_bounds__(256)
gemm_mma(const float* __restrict__ tokens, const float* __restrict__ wsel) {
    extern __shared__ float sm[];

    const int t    = threadIdx.x;
    const int lane = t & 31;
    const int wid  = t >> 5;
    const int warp_m = wid & 3;           // 0..3 -> token offset *32
    const int warp_n = wid >> 2;          // 0..1 -> expert offset *32
    const int g  = lane >> 2;             // 0..7
    const int tg = lane & 3;              // 0..3
    const int n0 = blockIdx.x * BMt;

    // loader coords: A 4 float4/thread (128x8 f4), B 2 float4/thread (64x8 f4)
    const float* asrc[4];
    uint32_t adst[4];
    #pragma unroll
    for (int r = 0; r < 4; r++) {
        int i = t + r * 256;
        int row = i >> 3, kq = i & 7;
        asrc[r] = tokens + (size_t)(n0 + row) * D_DIM + kq * 4;
        adst[r] = (uint32_t)(row * ASTR + kq * 4);
    }
    const float* bsrc[2];
    uint32_t bdst[2];
    #pragma unroll
    for (int r = 0; r < 2; r++) {
        int i = t + r * 256;
        int row = i >> 3, kq = i & 7;
        bsrc[r] = wsel + (size_t)row * D_DIM + kq * 4;
        bdst[r] = (uint32_t)(A_FLOATS + row * ASTR + kq * 4);
    }

    float c[2][4][4];
    #pragma unroll
    for (int mi = 0; mi < 2; mi++)
        #pragma unroll
        for (int ni = 0; ni < 4; ni++)
            #pragma unroll
            for (int q = 0; q < 4; q++) c[mi][ni][q] = 0.0f;

    auto issue_loads = [&](int ch) {
        float* base = sm + (size_t)(ch & (STAGES - 1)) * STG_FLOATS;
        uint32_t b32 = smem_u32(base);
        int c0 = ch * BKt;
        #pragma unroll
        for (int r = 0; r < 4; r++)
            CP_ASYNC16(b32 + adst[r] * 4, asrc[r] + c0);
        #pragma unroll
        for (int r = 0; r < 2; r++)
            CP_ASYNC16(b32 + bdst[r] * 4, bsrc[r] + c0);
    };

    // prologue: stages 0..STAGES-2 in flight
    #pragma unroll
    for (int s = 0; s < STAGES - 1; s++) { issue_loads(s); CP_COMMIT(); }

    for (int ch = 0; ch < NCHUNK; ch++) {
        CP_WAIT(STAGES - 2);          // chunk ch arrived (empty commits keep count)
        __syncthreads();
        int pre = ch + STAGES - 1;
        if (pre < NCHUNK) issue_loads(pre);
        CP_COMMIT();                  // commit every iteration (possibly empty)

        const float* Ab = sm + (size_t)(ch & (STAGES - 1)) * STG_FLOATS;
        const float* Bb = Ab + A_FLOATS;
        #pragma unroll
        for (int ks = 0; ks < 4; ks++) {
            const int kc = ks * 8;
            uint32_t ahi[2][4], alo[2][4], bhi[4][2], blo[4][2];
            #pragma unroll
            for (int mi = 0; mi < 2; mi++) {
                int r0 = warp_m * 32 + mi * 16 + g;
                split(Ab[r0 * ASTR + kc + tg],           ahi[mi][0], alo[mi][0]);
                split(Ab[(r0 + 8) * ASTR + kc + tg],     ahi[mi][1], alo[mi][1]);
                split(Ab[r0 * ASTR + kc + tg + 4],       ahi[mi][2], alo[mi][2]);
                split(Ab[(r0 + 8) * ASTR + kc + tg + 4], ahi[mi][3], alo[mi][3]);
            }
            #pragma unroll
            for (int ni = 0; ni < 4; ni++) {
                int cb = warp_n * 32 + ni * 8 + g;
                split(Bb[cb * ASTR + kc + tg],     bhi[ni][0], blo[ni][0]);
                split(Bb[cb * ASTR + kc + tg + 4], bhi[ni][1], blo[ni][1]);
            }
            #pragma unroll
            for (int mi = 0; mi < 2; mi++)
                #pragma unroll
                for (int ni = 0; ni < 4; ni++) {
                    mma_tf32(c[mi][ni], ahi[mi], bhi[ni]);
                    mma_tf32(c[mi][ni], ahi[mi], blo[ni]);
                    mma_tf32(c[mi][ni], alo[mi], bhi[ni]);
                }
        }
    }

    // ---- epilogue: c[mi][ni] -> g_aff[e][token] ----
    #pragma unroll
    for (int mi = 0; mi < 2; mi++) {
        int tm = n0 + warp_m * 32 + mi * 16;
        #pragma unroll
        for (int ni = 0; ni < 4; ni++) {
            int en = warp_n * 32 + ni * 8 + 2 * tg;
            g_aff[(size_t)en       * N_TOK + tm + g    ] = c[mi][ni][0];
            g_aff[(size_t)(en + 1) * N_TOK + tm + g    ] = c[mi][ni][1];
            g_aff[(size_t)en       * N_TOK + tm + g + 8] = c[mi][ni][2];
            g_aff[(size_t)(en + 1) * N_TOK + tm + g + 8] = c[mi][ni][3];
        }
    }
}

// ---------------------------------------------------------------------------
// Kernel 2: per-expert exact top-256 + softmax -> compact lists + counts.
// One CTA (1024 threads) per expert; smem score cache; after pass 1, a
// candidate list (top-bits >= b1, ~hundreds of entries) replaces the five
// remaining full 16K scans. Fallback to full scans if the list overflows.
// ---------------------------------------------------------------------------
__global__ void __launch_bounds__(1024)
topk_kernel() {
    extern __shared__ float scores[];          // N_TOK floats = 64 KB

    __shared__ unsigned hist[2048];
    __shared__ unsigned short cand[CANDMAX];   // 16 KB
    __shared__ unsigned gsum[64];
    __shared__ unsigned wred[32];
    __shared__ float    fwred[32];
    __shared__ unsigned eqidx[256];
    __shared__ unsigned s_neq, s_na, s_ncand;
    __shared__ unsigned s_b1, s_ab1, s_b2, s_ab2, s_T, s_needeq, s_maxkey;
    __shared__ float    s_m, s_scoreT, s_inv;

    const int e = blockIdx.x;
    const int t = threadIdx.x;
    const float* row = g_aff + (size_t)e * N_TOK;

    // ---- pass 1: load + histogram (top 11 bits) + row max ----
    for (int i = t; i < 2048; i += 1024) hist[i] = 0;
    if (t == 0) { s_neq = 0; s_na = 0; s_ncand = 0; }
    __syncthreads();

    unsigned kmax = 0;
    for (int i = t; i < N_TOK; i += 1024) {
        float s = row[i];
        scores[i] = s;
        unsigned k = f2k(s);
        kmax = max(kmax, k);
        unsigned bin = k >> 21;
        unsigned mask = __match_any_sync(0xFFFFFFFFu, bin);
        int leader = __ffs(mask) - 1;
        if ((t & 31) == leader) atomicAdd(&hist[bin], (unsigned)__popc(mask));
    }
    #pragma unroll
    for (int o = 16; o; o >>= 1) kmax = max(kmax, __shfl_xor_sync(0xFFFFFFFFu, kmax, o));
    if ((t & 31) == 0) wred[t >> 5] = kmax;
    __syncthreads();
    if (t < 32) {
        unsigned v = wred[t];
        #pragma unroll
        for (int o = 16; o; o >>= 1) v = max(v, __shfl_xor_sync(0xFFFFFFFFu, v, o));
        if (t == 0) s_maxkey = v;
    }
    if (t < 64) { unsigned s = 0; for (int j = 0; j < 32; j++) s += hist[t * 32 + j]; gsum[t] = s; }
    __syncthreads();
    if (t == 0) {
        unsigned need = CAP, cum = 0; int g = 63;
        for (; g > 0; g--) { if (cum + gsum[g] >= need) break; cum += gsum[g]; }
        int b = g * 32 + 31;
        for (; b > g * 32; b--) { if (cum + hist[b] >= need) break; cum += hist[b]; }
        s_b1 = (unsigned)b; s_ab1 = cum;
    }
    __syncthreads();
    const unsigned b1 = s_b1, ab1 = s_ab1;

    // ---- build candidate list: all i with top-11-bits >= b1 ----
    for (int i = t; i < N_TOK; i += 1024) {
        unsigned k = f2k(scores[i]);
        if ((k >> 21) >= b1) {
            unsigned p = atomicAdd(&s_ncand, 1u);
            if (p < CANDMAX) cand[p] = (unsigned short)i;
        }
    }
    __syncthreads();
    const unsigned ncr = s_ncand;
    const bool use_c = (ncr <= CANDMAX);
    const int lim = use_c ? (int)ncr : N_TOK;

    // ---- pass 2: next 11 bits within bin b1 ----
    for (int i = t; i < 2048; i += 1024) hist[i] = 0;
    __syncthreads();
    for (int j = t; j < lim; j += 1024) {
        int i = use_c ? (int)cand[j] : j;
        unsigned k = f2k(scores[i]);
        if ((k >> 21) == b1) atomicAdd(&hist[(k >> 10) & 0x7FFu], 1u);
    }
    __syncthreads();
    if (t < 64) { unsigned s = 0; for (int j = 0; j < 32; j++) s += hist[t * 32 + j]; gsum[t] = s; }
    __syncthreads();
    if (t == 0) {
        unsigned need = CAP - ab1, cum = 0; int g = 63;
        for (; g > 0; g--) { if (cum + gsum[g] >= need) break; cum += gsum[g]; }
        int b = g * 32 + 31;
        for (; b > g * 32; b--) { if (cum + hist[b] >= need) break; cum += hist[b]; }
        s_b2 = (unsigned)b; s_ab2 = ab1 + cum;
    }
    __syncthreads();
    const unsigned b2 = s_b2, ab2 = s_ab2;
    const unsigned pref = (b1 << 11) | b2;

    // ---- pass 3: low 10 bits ----
    if (t < 1024) hist[t] = 0;
    __syncthreads();
    for (int j = t; j < lim; j += 1024) {
        int i = use_c ? (int)cand[j] : j;
        unsigned k = f2k(scores[i]);
        if ((k >> 10) == pref) atomicAdd(&hist[k & 0x3FFu], 1u);
    }
    __syncthreads();
    if (t < 32) { unsigned s = 0; for (int j = 0; j < 32; j++) s += hist[t * 32 + j]; gsum[t] = s; }
    __syncthreads();
    if (t == 0) {
        unsigned need = CAP - ab2, cum = 0; int g = 31;
        for (; g > 0; g--) { if (cum + gsum[g] >= need) break; cum += gsum[g]; }
        int b = g * 32 + 31;
        for (; b > g * 32; b--) { if (cum + hist[b] >= need) break; cum += hist[b]; }
        unsigned T = (pref << 10) | (unsigned)b;
        s_T = T;
        s_needeq = CAP - (ab2 + cum);
    }
    __syncthreads();
    const unsigned T = s_T;
    const unsigned need_eq = s_needeq;

    // ---- collect indices with key == T (all such i are candidates) ----
    for (int j = t; j < lim; j += 1024) {
        int i = use_c ? (int)cand[j] : j;
        if (f2k(scores[i]) == T) {
            unsigned p = atomicAdd(&s_neq, 1u);
            if (p < 256) eqidx[p] = (unsigned)i;
        }
    }
    __syncthreads();
    if (t == 0) {
        unsigned ne = min(s_neq, 256u);
        for (unsigned s = 0; s < need_eq && s < ne; s++) {  // smallest indices first
            unsigned mi = s;
            for (unsigned j = s + 1; j < ne; j++)
                if (eqidx[j] < eqidx[mi]) mi = j;
            unsigned tmp = eqidx[s]; eqidx[s] = eqidx[mi]; eqidx[mi] = tmp;
        }
        s_m = k2f(s_maxkey);
        s_scoreT = k2f(T);
    }
    __syncthreads();
    const float m = s_m;

    // ---- softmax denominator over selected set (all > T are candidates) ----
    float part = 0.0f;
    for (int j = t; j < lim; j += 1024) {
        int i = use_c ? (int)cand[j] : j;
        if (f2k(scores[i]) > T) part += expf(scores[i] - m);
    }
    #pragma unroll
    for (int o = 16; o; o >>= 1) part += __shfl_xor_sync(0xFFFFFFFFu, part, o);
    if ((t & 31) == 0) fwred[t >> 5] = part;
    __syncthreads();
    if (t < 32) {
        float v = fwred[t];
        #pragma unroll
        for (int o = 16; o; o >>= 1) v += __shfl_xor_sync(0xFFFFFFFFu, v, o);
        if (t == 0) s_inv = 1.0f / (v + (float)need_eq * expf(s_scoreT - m));
    }
    __syncthreads();
    const float inv = s_inv;

    // ---- compact output ----
    unsigned* sel_i = g_sel_idx  + (size_t)e * CAP;
    float*    sel_p = g_sel_prob + (size_t)e * CAP;
    for (int j = t; j < lim; j += 1024) {
        int i = use_c ? (int)cand[j] : j;
        if (f2k(scores[i]) > T) {
            unsigned pos = atomicAdd(&s_na, 1u);
            sel_i[pos] = (unsigned)i;
            sel_p[pos] = expf(scores[i] - m) * inv;
            atomicAdd(&g_counts[i], 1);
        }
    }
    __syncthreads();
    unsigned ne = min(s_neq, 256u);
    if (t < (int)need_eq && t < (int)ne) {
        unsigned i = eqidx[t];
        unsigned pos = (CAP - need_eq) + t;
        sel_i[pos] = i;
        sel_p[pos] = expf(s_scoreT - m) * inv;
        atomicAdd(&g_counts[i], 1);
    }
}

// ---------------------------------------------------------------------------
// Kernel 3: emit — scatter compact lists into [N,E] outputs with count divide
// ---------------------------------------------------------------------------
__global__ void emit_kernel(float* __restrict__ out_w, float* __restrict__ out_a) {
    int idx = blockIdx.x * blockDim.x + threadIdx.x;
    if (idx >= E_EXP * CAP) return;
    int e = idx >> 8;                                  // CAP == 256
    unsigned i = g_sel_idx[idx];
    float p = g_sel_prob[idx];
    int c = g_counts[i];
    out_w[(size_t)i * E_EXP + e] = p / (float)c;
    out_a[(size_t)i * E_EXP + e] = 1.0f;
}

// ---------------------------------------------------------------------------
// launch
// ---------------------------------------------------------------------------
extern "C" void kernel_launch(void* const* d_in, const int* in_sizes, int n_in,
                              void* d_out, int out_size) {
    const float* tokens = (const float*)d_in[0];   // [4,4096,2048] fp32
    const float* wsel   = (const float*)d_in[1];   // [64,2048] fp32
    float* out = (float*)d_out;

    const int total_main = 2 * N_TOK * E_EXP;

    float* out_w;
    float* out_a;
    float* dummy_ptr = nullptr;
    cudaGetSymbolAddress((void**)&dummy_ptr, g_dummy);
    if (out_size >= total_main) {
        out_w = out;
        out_a = out + (size_t)N_TOK * E_EXP;
    } else if (out_size >= N_TOK * E_EXP) {
        out_w = out;
        out_a = dummy_ptr;
    } else {
        out_w = dummy_ptr;
        out_a = dummy_ptr;
    }

    cudaFuncSetAttribute(gemm_mma, cudaFuncAttributeMaxDynamicSharedMemorySize, GEMM_SMEM);
    cudaFuncSetAttribute(topk_kernel, cudaFuncAttributeMaxDynamicSharedMemorySize,
                         N_TOK * sizeof(float));

    // 0) init outputs + counts
    {
        int quads = (out_size + 3) / 4;
        int blocks = (quads + 255) / 256;
        init_kernel<<<blocks, 256>>>(out, out_size, total_main);
    }
    // 1) TF32x3 mma.sync GEMM (4-stage cp.async) -> g_aff
    gemm_mma<<<N_TOK / BMt, 256, GEMM_SMEM>>>(tokens, wsel);
    // 2) per-expert top-256 + softmax -> compact lists + counts
    topk_kernel<<<E_EXP, 1024, N_TOK * sizeof(float)>>>();
    // 3) emit outputs
    emit_kernel<<<(E_EXP * CAP + 127) / 128, 128>>>(out_w, out_a);
}